// round 2
// baseline (speedup 1.0000x reference)
#include <cuda_runtime.h>

// Shape (fixed by reference)
#define B_   16
#define T_   4096
#define D_   512
#define L_   128              // chunk length (t-steps per block)
#define C_   (T_ / L_)        // 32 chunks per series
#define DG_  128              // d-lanes per block
#define NDG  (D_ / DG_)       // 4 d-groups
#define NCHAIN (B_ * NDG)     // 64 independent carry chains

// Cross-block scratch (static __device__; zero-init at module load; flags are
// consumer-cleared so every graph replay starts from the all-zero state).
__device__ float2 g_incl[(size_t)NCHAIN * C_ * DG_];  // inclusive chunk states, 1 MB
__device__ int    g_flag[NCHAIN * C_];                // publish flags

// ---------------------------------------------------------------------------
// Single fused kernel: chained chunk scan with SMEM-stashed x tiles.
//   grid  = NCHAIN * C_ = 2048 blocks, 1D; bid = chain*C_ + c so that each
//           block depends only on bid-1 (forward-progress safe).
//   block = 128 threads (one per d-lane in the group). 64 KB dynamic smem.
// Phases: (1) bulk-load x tile -> smem, (2) local scan from zero -> aggregate,
// (3) wait pred inclusive (carry), (4) publish own inclusive via A^128 jump,
// (5) rescan tile from smem with carry init, streaming-store outputs.
// ---------------------------------------------------------------------------
__global__ void __launch_bounds__(DG_) fused_scan_kernel(
    const float* __restrict__ x,
    const float* __restrict__ Ar,
    const float* __restrict__ Ai,
    float2* __restrict__ out)
{
    extern __shared__ float s[];            // [L_][DG_] = 64 KB
    const int tid   = threadIdx.x;
    const int bid   = blockIdx.x;
    const int c     = bid & (C_ - 1);
    const int chain = bid >> 5;             // / C_
    const int dg    = chain & (NDG - 1);
    const int b     = chain >> 2;           // / NDG
    const int dglob = dg * DG_ + tid;

    const float ar = Ar[dglob];
    const float ai = Ai[dglob];

    // --- (1) load x tile (read-once: .cs) -----------------------------------
    const float* xb = x + ((size_t)b * T_ + (size_t)c * L_) * D_ + dg * DG_;
    {
        const int lane4 = tid & 31;         // float4 column within the 512B row-segment
        const int rsub  = tid >> 5;         // 0..3: row within group of 4
        float4* s4 = (float4*)s;
        #pragma unroll
        for (int r = 0; r < L_ / 4; ++r) {
            const int row = r * 4 + rsub;
            float4 v = __ldcs((const float4*)(xb + (size_t)row * D_) + lane4);
            s4[row * (DG_ / 4) + lane4] = v;
        }
    }
    __syncthreads();

    // --- (2) local scan from zero -> per-thread aggregate -------------------
    float sr = 0.0f, si = 0.0f;
    #pragma unroll 8
    for (int t = 0; t < L_; ++t) {
        const float xv = s[t * DG_ + tid];
        const float nr = fmaf(sr, ar, fmaf(-si, ai, xv));
        const float ni = fmaf(sr, ai, si * ar);
        sr = nr; si = ni;
    }

    // --- (3) acquire carry = predecessor's inclusive state ------------------
    float cr = 0.0f, ci = 0.0f;
    if (c > 0) {
        volatile int* f = &g_flag[chain * C_ + c - 1];
        if (tid == 0) { while (*f == 0) { __nanosleep(40); } }
        __syncthreads();
        __threadfence();                    // order carry reads after flag observation
        const float2 cv = __ldcg(&g_incl[((size_t)chain * C_ + (c - 1)) * DG_ + tid]);
        cr = cv.x; ci = cv.y;
        __syncthreads();                    // everyone has read before the clear
        if (tid == 0) *f = 0;               // consumer-clear: replay-deterministic
    }

    // --- (4) publish own inclusive (A^128 jump; off the heavy-memory path) --
    if (c < C_ - 1) {
        float pr = ar, pi = ai;
        #pragma unroll
        for (int k = 0; k < 7; ++k) {       // A^(2^7) = A^128
            const float nr = pr * pr - pi * pi;
            const float ni = 2.0f * pr * pi;
            pr = nr; pi = ni;
        }
        const float ir = fmaf(pr, cr, fmaf(-pi, ci, sr));
        const float ii = fmaf(pi, cr, fmaf(pr, ci, si));
        g_incl[((size_t)chain * C_ + c) * DG_ + tid] = make_float2(ir, ii);
        __threadfence();                    // make value globally visible ...
        __syncthreads();                    // ... from every thread, before the flag
        if (tid == 0) atomicExch(&g_flag[chain * C_ + c], 1);
    }

    // --- (5) rescan from smem with carry init; stream outputs ---------------
    float2* ob = out + ((size_t)b * T_ + (size_t)c * L_) * D_ + dg * DG_ + tid;
    sr = cr; si = ci;
    #pragma unroll 4
    for (int t = 0; t < L_; ++t) {
        const float xv = s[t * DG_ + tid];
        const float nr = fmaf(sr, ar, fmaf(-si, ai, xv));
        const float ni = fmaf(sr, ai, si * ar);
        sr = nr; si = ni;
        __stcs(&ob[(size_t)t * D_], make_float2(nr, ni));
    }
}

// ---------------------------------------------------------------------------
// Inputs (metadata order): x [B*T*D] f32, A_real [D] f32, A_imag [D] f32.
// Output: [B, T, D, 2] f32.
// ---------------------------------------------------------------------------
extern "C" void kernel_launch(void* const* d_in, const int* in_sizes, int n_in,
                              void* d_out, int out_size)
{
    const float* x  = (const float*)d_in[0];
    const float* Ar = (const float*)d_in[1];
    const float* Ai = (const float*)d_in[2];
    float2* out = (float2*)d_out;

    const int smem = L_ * DG_ * (int)sizeof(float);   // 64 KB
    static bool attr_set = false;
    if (!attr_set) {
        cudaFuncSetAttribute(fused_scan_kernel,
                             cudaFuncAttributeMaxDynamicSharedMemorySize, smem);
        attr_set = true;
    }
    fused_scan_kernel<<<NCHAIN * C_, DG_, smem>>>(x, Ar, Ai, out);
}

// round 3
// speedup vs baseline: 1.7113x; 1.7113x over previous
#include <cuda_runtime.h>

// Shape (fixed by reference)
#define B_     16
#define T_     4096
#define D_     512
#define L_     64                 // t-steps per block tile
#define HALF_  32                 // t-steps per half (2 halves per block)
#define DG_    128                // d-lanes per block
#define NDG    (D_ / DG_)         // 4
#define C_     (T_ / L_)          // 64 chunks per chain
#define NCHAIN (B_ * NDG)         // 64 chains
#define NBLK   (NCHAIN * C_)      // 4096 blocks
#define THREADS 256

// Decoupled-lookback state (static __device__ scratch; flags re-zeroed per launch)
__device__ float2 g_agg [(size_t)NBLK * DG_];   // local aggregates   (4 MB)
__device__ float2 g_incl[(size_t)NBLK * DG_];   // inclusive prefixes (4 MB)
__device__ int    g_flag[NBLK];                 // 0=none, 1=agg, 2=inclusive

__global__ void init_flags_kernel()
{
    g_flag[blockIdx.x * THREADS + threadIdx.x] = 0;
}

// ---------------------------------------------------------------------------
// Fused decoupled-lookback scan.
//   bid = chain*C_ + c  (predecessors dispatch first).
//   256 threads = 2 t-halves x 128 d-lanes. 32KB smem x-stash.
// ---------------------------------------------------------------------------
__global__ void __launch_bounds__(THREADS) scan_kernel(
    const float* __restrict__ x,
    const float* __restrict__ Ar,
    const float* __restrict__ Ai,
    float2* __restrict__ out)
{
    __shared__ float  sx[L_ * DG_];      // 32 KB x tile, [t][d]
    __shared__ float2 se[2 * DG_];       // half-end states

    const int tid   = threadIdx.x;
    const int bid   = blockIdx.x;
    const int c     = bid & (C_ - 1);
    const int chain = bid >> 6;                 // / C_
    const int dg    = chain & (NDG - 1);
    const int b     = chain >> 2;               // / NDG
    const int d     = tid & (DG_ - 1);
    const int h     = tid >> 7;                 // 0 or 1: which t-half
    const int dglob = dg * DG_ + d;

    const float ar = Ar[dglob];
    const float ai = Ai[dglob];

    // ---- load x tile (streaming, float4) -----------------------------------
    const float* xb = x + ((size_t)b * T_ + (size_t)c * L_) * D_ + dg * DG_;
    {
        const int lane4 = tid & 31;             // float4 column (32 per row)
        const int rsub  = tid >> 5;             // 0..7
        float4* s4 = (float4*)sx;
        #pragma unroll
        for (int r = 0; r < L_ / 8; ++r) {
            const int row = r * 8 + rsub;
            s4[row * (DG_ / 4) + lane4] =
                __ldcs((const float4*)(xb + (size_t)row * D_) + lane4);
        }
    }
    __syncthreads();

    // ---- local scan of my half from zero -----------------------------------
    const float* sxh = sx + h * HALF_ * DG_ + d;
    float er = 0.0f, ei = 0.0f;
    #pragma unroll
    for (int t = 0; t < HALF_; ++t) {
        const float xv = sxh[t * DG_];
        const float nr = fmaf(er, ar, fmaf(-ei, ai, xv));
        const float ni = fmaf(er, ai, ei * ar);
        er = nr; ei = ni;
    }
    se[h * DG_ + d] = make_float2(er, ei);
    __syncthreads();

    // ---- A^32 (5 squarings), A^64 -------------------------------------------
    float p32r = ar, p32i = ai;
    #pragma unroll
    for (int k = 0; k < 5; ++k) {
        const float nr = p32r * p32r - p32i * p32i;
        const float ni = 2.0f * p32r * p32i;
        p32r = nr; p32i = ni;
    }
    const float p64r = p32r * p32r - p32i * p32i;
    const float p64i = 2.0f * p32r * p32i;

    // ---- block aggregate = E1 + A^32 * E0 -----------------------------------
    const float2 e0 = se[d];
    const float2 e1 = se[DG_ + d];
    const float aggr = fmaf(p32r, e0.x, fmaf(-p32i, e0.y, e1.x));
    const float aggi = fmaf(p32i, e0.x, fmaf( p32r, e0.y, e1.y));

    // ---- publish: c==0 publishes inclusive directly; middle blocks agg ------
    if (c == 0) {
        if (tid < DG_) g_incl[(size_t)bid * DG_ + d] = make_float2(aggr, aggi);
        __threadfence();
        __syncthreads();
        if (tid == 0) atomicExch(&g_flag[bid], 2);
    } else if (c < C_ - 1) {
        if (tid < DG_) g_agg[(size_t)bid * DG_ + d] = make_float2(aggr, aggi);
        __threadfence();
        __syncthreads();
        if (tid == 0) atomicExch(&g_flag[bid], 1);
    }

    // ---- lookback: carry = sum_k A^(64k) * agg/incl of predecessors ---------
    float cr = 0.0f, ci = 0.0f;
    if (c > 0) {
        float mr = 1.0f, mi = 0.0f;   // running multiplier A^(64*steps)
        int j = bid - 1;
        while (true) {
            volatile int* f = &g_flag[j];
            int v = *f;
            while (v == 0) { __nanosleep(50); v = *f; }
            __threadfence();          // acquire: order value loads after flag
            const float2 val = (v == 2)
                ? __ldcg(&g_incl[(size_t)j * DG_ + d])
                : __ldcg(&g_agg [(size_t)j * DG_ + d]);
            cr = fmaf(mr, val.x, fmaf(-mi, val.y, cr));
            ci = fmaf(mi, val.x, fmaf( mr, val.y, ci));
            if (v == 2) break;        // prefix complete
            const float nmr = mr * p64r - mi * p64i;
            const float nmi = mr * p64i + mi * p64r;
            mr = nmr; mi = nmi;
            --j;
        }
    }

    // ---- publish inclusive = A^64*carry + agg -------------------------------
    if (c > 0 && c < C_ - 1) {
        const float inr = fmaf(p64r, cr, fmaf(-p64i, ci, aggr));
        const float ini = fmaf(p64i, cr, fmaf( p64r, ci, aggi));
        if (tid < DG_) g_incl[(size_t)bid * DG_ + d] = make_float2(inr, ini);
        __threadfence();
        __syncthreads();
        if (tid == 0) atomicExch(&g_flag[bid], 2);
    }

    // ---- rescan my half from its true carry; stream out ---------------------
    float hr, hi;
    if (h == 0) { hr = cr; hi = ci; }
    else {
        // carry into half1 = A^32 * carry + E0
        hr = fmaf(p32r, cr, fmaf(-p32i, ci, e0.x));
        hi = fmaf(p32i, cr, fmaf( p32r, ci, e0.y));
    }
    float2* ob = out + ((size_t)b * T_ + (size_t)c * L_ + h * HALF_) * D_ + dglob;
    #pragma unroll
    for (int t = 0; t < HALF_; ++t) {
        const float xv = sxh[t * DG_];
        const float nr = fmaf(hr, ar, fmaf(-hi, ai, xv));
        const float ni = fmaf(hr, ai, hi * ar);
        hr = nr; hi = ni;
        __stcs(&ob[(size_t)t * D_], make_float2(nr, ni));
    }
}

// ---------------------------------------------------------------------------
// Inputs (metadata order): x [B*T*D] f32, A_real [D] f32, A_imag [D] f32.
// Output: [B, T, D, 2] f32.
// ---------------------------------------------------------------------------
extern "C" void kernel_launch(void* const* d_in, const int* in_sizes, int n_in,
                              void* d_out, int out_size)
{
    const float* x  = (const float*)d_in[0];
    const float* Ar = (const float*)d_in[1];
    const float* Ai = (const float*)d_in[2];
    float2* out = (float2*)d_out;

    init_flags_kernel<<<NBLK / THREADS, THREADS>>>();
    scan_kernel<<<NBLK, THREADS>>>(x, Ar, Ai, out);
}

// round 4
// speedup vs baseline: 2.3840x; 1.3931x over previous
#include <cuda_runtime.h>

// Shape (fixed by reference)
#define B_     16
#define T_     4096
#define D_     512
#define L_     64                 // t-steps per block tile
#define HALF_  32                 // t-steps per half (2 halves per block)
#define DG_    128                // d-lanes per block
#define NDG    (D_ / DG_)         // 4
#define C_     (T_ / L_)          // 64 chunks per chain
#define NCHAIN (B_ * NDG)         // 64 chains
#define NBLK   (NCHAIN * C_)      // 4096 blocks
#define THREADS 256

// Decoupled-lookback state (static __device__ scratch; flags re-zeroed per launch)
__device__ float2 g_agg [(size_t)NBLK * DG_];   // local aggregates   (4 MB)
__device__ float2 g_incl[(size_t)NBLK * DG_];   // inclusive prefixes (4 MB)
__device__ int    g_flag[NBLK];                 // 0=none, 1=agg, 2=inclusive

__global__ void init_flags_kernel()
{
    g_flag[blockIdx.x * THREADS + threadIdx.x] = 0;
}

// ---------------------------------------------------------------------------
// Fused decoupled-lookback scan.
//   bid = c*NCHAIN + chain  (CRITICAL: waves span all chains at the same small
//   c-range, so lookback depth <= blocks-per-chain-per-wave ~ 13, and
//   predecessors dispatched NCHAIN bids earlier are already resident/retired).
//   256 threads = 2 t-halves x 128 d-lanes. 32KB smem x-stash.
// ---------------------------------------------------------------------------
__global__ void __launch_bounds__(THREADS) scan_kernel(
    const float* __restrict__ x,
    const float* __restrict__ Ar,
    const float* __restrict__ Ai,
    float2* __restrict__ out)
{
    __shared__ float  sx[L_ * DG_];      // 32 KB x tile, [t][d]
    __shared__ float2 se[2 * DG_];       // half-end states
    __shared__ float2 scarry[DG_];       // block carry (shared h0 -> h1)

    const int tid   = threadIdx.x;
    const int bid   = blockIdx.x;
    const int chain = bid & (NCHAIN - 1);       // % 64
    const int c     = bid >> 6;                 // / 64
    const int dg    = chain & (NDG - 1);
    const int b     = chain >> 2;               // / NDG
    const int d     = tid & (DG_ - 1);
    const int h     = tid >> 7;                 // 0 or 1: which t-half
    const int dglob = dg * DG_ + d;

    const float ar = Ar[dglob];
    const float ai = Ai[dglob];

    // ---- load x tile (streaming, float4) -----------------------------------
    const float* xb = x + ((size_t)b * T_ + (size_t)c * L_) * D_ + dg * DG_;
    {
        const int lane4 = tid & 31;             // float4 column (32 per row)
        const int rsub  = tid >> 5;             // 0..7
        float4* s4 = (float4*)sx;
        #pragma unroll
        for (int r = 0; r < L_ / 8; ++r) {
            const int row = r * 8 + rsub;
            s4[row * (DG_ / 4) + lane4] =
                __ldcs((const float4*)(xb + (size_t)row * D_) + lane4);
        }
    }
    __syncthreads();

    // ---- local scan of my half from zero -----------------------------------
    const float* sxh = sx + h * HALF_ * DG_ + d;
    float er = 0.0f, ei = 0.0f;
    #pragma unroll
    for (int t = 0; t < HALF_; ++t) {
        const float xv = sxh[t * DG_];
        const float nr = fmaf(er, ar, fmaf(-ei, ai, xv));
        const float ni = fmaf(er, ai, ei * ar);
        er = nr; ei = ni;
    }
    se[h * DG_ + d] = make_float2(er, ei);
    __syncthreads();

    // ---- A^32 (5 squarings), A^64 -------------------------------------------
    float p32r = ar, p32i = ai;
    #pragma unroll
    for (int k = 0; k < 5; ++k) {
        const float nr = p32r * p32r - p32i * p32i;
        const float ni = 2.0f * p32r * p32i;
        p32r = nr; p32i = ni;
    }
    const float p64r = p32r * p32r - p32i * p32i;
    const float p64i = 2.0f * p32r * p32i;

    // ---- block aggregate = E1 + A^32 * E0 -----------------------------------
    const float2 e0 = se[d];
    const float2 e1 = se[DG_ + d];
    const float aggr = fmaf(p32r, e0.x, fmaf(-p32i, e0.y, e1.x));
    const float aggi = fmaf(p32i, e0.x, fmaf( p32r, e0.y, e1.y));

    // ---- publish: c==0 publishes inclusive directly; middle blocks agg ------
    if (c == 0) {
        if (tid < DG_) g_incl[(size_t)bid * DG_ + d] = make_float2(aggr, aggi);
        __threadfence();
        __syncthreads();
        if (tid == 0) atomicExch(&g_flag[bid], 2);
    } else if (c < C_ - 1) {
        if (tid < DG_) g_agg[(size_t)bid * DG_ + d] = make_float2(aggr, aggi);
        __threadfence();
        __syncthreads();
        if (tid == 0) atomicExch(&g_flag[bid], 1);
    }

    // ---- lookback (h=0 threads only): carry = sum A^(64k)*agg until incl ----
    float cr = 0.0f, ci = 0.0f;
    if (c > 0) {
        if (tid < DG_) {
            float mr = 1.0f, mi = 0.0f;         // running multiplier A^(64k)
            int j = bid - NCHAIN;               // predecessor chunk, same chain
            while (true) {
                volatile int* f = &g_flag[j];
                int v = *f;
                while (v == 0) { __nanosleep(40); v = *f; }
                __threadfence();                // acquire
                const float2 val = (v == 2)
                    ? __ldcg(&g_incl[(size_t)j * DG_ + d])
                    : __ldcg(&g_agg [(size_t)j * DG_ + d]);
                cr = fmaf(mr, val.x, fmaf(-mi, val.y, cr));
                ci = fmaf(mi, val.x, fmaf( mr, val.y, ci));
                if (v == 2) break;              // prefix complete
                const float nmr = mr * p64r - mi * p64i;
                const float nmi = mr * p64i + mi * p64r;
                mr = nmr; mi = nmi;
                j -= NCHAIN;
            }
            scarry[d] = make_float2(cr, ci);
            // publish inclusive = A^64*carry + agg
            if (c < C_ - 1) {
                const float inr = fmaf(p64r, cr, fmaf(-p64i, ci, aggr));
                const float ini = fmaf(p64i, cr, fmaf( p64r, ci, aggi));
                g_incl[(size_t)bid * DG_ + d] = make_float2(inr, ini);
                __threadfence();
            }
        }
        __syncthreads();
        if (c < C_ - 1 && tid == 0) atomicExch(&g_flag[bid], 2);
        const float2 cv = scarry[d];
        cr = cv.x; ci = cv.y;
    }

    // ---- rescan my half from its true carry; stream out ---------------------
    float hr, hi;
    if (h == 0) { hr = cr; hi = ci; }
    else {
        // carry into half1 = A^32 * carry + E0
        hr = fmaf(p32r, cr, fmaf(-p32i, ci, e0.x));
        hi = fmaf(p32i, cr, fmaf( p32r, ci, e0.y));
    }
    float2* ob = out + ((size_t)b * T_ + (size_t)c * L_ + h * HALF_) * D_ + dglob;
    #pragma unroll
    for (int t = 0; t < HALF_; ++t) {
        const float xv = sxh[t * DG_];
        const float nr = fmaf(hr, ar, fmaf(-hi, ai, xv));
        const float ni = fmaf(hr, ai, hi * ar);
        hr = nr; hi = ni;
        __stcs(&ob[(size_t)t * D_], make_float2(nr, ni));
    }
}

// ---------------------------------------------------------------------------
// Inputs (metadata order): x [B*T*D] f32, A_real [D] f32, A_imag [D] f32.
// Output: [B, T, D, 2] f32.
// ---------------------------------------------------------------------------
extern "C" void kernel_launch(void* const* d_in, const int* in_sizes, int n_in,
                              void* d_out, int out_size)
{
    const float* x  = (const float*)d_in[0];
    const float* Ar = (const float*)d_in[1];
    const float* Ai = (const float*)d_in[2];
    float2* out = (float2*)d_out;

    init_flags_kernel<<<NBLK / THREADS, THREADS>>>();
    scan_kernel<<<NBLK, THREADS>>>(x, Ar, Ai, out);
}

// round 5
// speedup vs baseline: 2.4740x; 1.0378x over previous
#include <cuda_runtime.h>

// Shape (fixed by reference)
#define B_     16
#define T_     4096
#define D_     512
#define L_     64                 // t-steps per block tile
#define HALF_  32                 // t-steps per half
#define DG_    128                // d-lanes per block
#define NDG    (D_ / DG_)         // 4
#define C_     (T_ / L_)          // 64 chunks per chain
#define NCHAIN (B_ * NDG)         // 64 chains
#define NBLK   (NCHAIN * C_)      // 4096 blocks
#define THREADS 256

// Decoupled-lookback state (static __device__ scratch; flags re-zeroed per launch)
__device__ float2 g_agg [(size_t)NBLK * DG_];   // local aggregates   (4 MB)
__device__ float2 g_incl[(size_t)NBLK * DG_];   // inclusive prefixes (4 MB)
__device__ int    g_flag[NBLK];                 // 0=none, 1=agg, 2=inclusive

__global__ void init_flags_kernel()
{
    g_flag[blockIdx.x * THREADS + threadIdx.x] = 0;
}

// ---------------------------------------------------------------------------
// Warp-specialized decoupled-lookback scan.
//   bid = c*NCHAIN + chain (waves span all chains -> shallow lookback).
//   Warps 4-7 (h=1): tile load -> full 64-step local scan -> publish agg.
//   Warps 0-3 (h=0): lookback runs CONCURRENTLY with the scan.
//   One __syncthreads joins; both halves rescan from the true carry and
//   stream outputs. 32 KB smem x-stash -> x is read from DRAM exactly once.
// ---------------------------------------------------------------------------
__global__ void __launch_bounds__(THREADS) scan_kernel(
    const float* __restrict__ x,
    const float* __restrict__ Ar,
    const float* __restrict__ Ai,
    float2* __restrict__ out)
{
    __shared__ float  sx[L_ * DG_];      // 32 KB x tile, [t][d]
    __shared__ float2 se0[DG_];          // state after half0 (zero-init scan)
    __shared__ float2 sagg[DG_];         // full-tile aggregate
    __shared__ float2 scarry[DG_];       // block carry from lookback

    const int tid   = threadIdx.x;
    const int bid   = blockIdx.x;
    const int chain = bid & (NCHAIN - 1);
    const int c     = bid >> 6;                 // / NCHAIN
    const int dg    = chain & (NDG - 1);
    const int b     = chain >> 2;               // / NDG
    const int d     = tid & (DG_ - 1);
    const int h     = tid >> 7;                 // 0: lookback+half0, 1: scan+half1
    const int dglob = dg * DG_ + d;

    const float ar = Ar[dglob];
    const float ai = Ai[dglob];

    // A^32 (5 squarings) and A^64 — cheap, computed by every thread.
    float p32r = ar, p32i = ai;
    #pragma unroll
    for (int k = 0; k < 5; ++k) {
        const float nr = p32r * p32r - p32i * p32i;
        const float ni = 2.0f * p32r * p32i;
        p32r = nr; p32i = ni;
    }
    const float p64r = p32r * p32r - p32i * p32i;
    const float p64i = 2.0f * p32r * p32i;

    if (h == 1) {
        // ===== producer half: tile load + local scan + agg publish ==========
        const float* xb = x + ((size_t)b * T_ + (size_t)c * L_) * D_ + dg * DG_;
        {
            const int lane4 = d & 31;           // float4 column (32 per row)
            const int rsub  = d >> 5;           // 0..3
            float4* s4 = (float4*)sx;
            #pragma unroll
            for (int r = 0; r < L_ / 4; ++r) {
                const int row = r * 4 + rsub;
                s4[row * (DG_ / 4) + lane4] =
                    __ldcs((const float4*)(xb + (size_t)row * D_) + lane4);
            }
        }
        asm volatile("bar.sync 1, 128;" ::: "memory");   // h1 group: tile ready

        const float* sxd = sx + d;
        float er = 0.0f, ei = 0.0f;
        #pragma unroll
        for (int t = 0; t < HALF_; ++t) {
            const float xv = sxd[t * DG_];
            const float nr = fmaf(er, ar, fmaf(-ei, ai, xv));
            const float ni = fmaf(er, ai, ei * ar);
            er = nr; ei = ni;
        }
        se0[d] = make_float2(er, ei);            // E0 = state after half0
        #pragma unroll
        for (int t = HALF_; t < L_; ++t) {
            const float xv = sxd[t * DG_];
            const float nr = fmaf(er, ar, fmaf(-ei, ai, xv));
            const float ni = fmaf(er, ai, ei * ar);
            er = nr; ei = ni;
        }
        sagg[d] = make_float2(er, ei);           // block aggregate

        if (c == 0) {                            // inclusive == aggregate
            g_incl[(size_t)bid * DG_ + d] = make_float2(er, ei);
            __threadfence();
            asm volatile("bar.sync 1, 128;" ::: "memory");
            if (d == 0) atomicExch(&g_flag[bid], 2);
        } else if (c < C_ - 1) {
            g_agg[(size_t)bid * DG_ + d] = make_float2(er, ei);
            __threadfence();
            asm volatile("bar.sync 1, 128;" ::: "memory");
            if (d == 0) atomicExch(&g_flag[bid], 1);
        }
    } else {
        // ===== lookback half: runs concurrently with the scan above =========
        float cr = 0.0f, ci = 0.0f;
        if (c > 0) {
            float mr = 1.0f, mi = 0.0f;          // running multiplier A^(64k)
            int j = bid - NCHAIN;                // predecessor chunk, same chain
            while (true) {
                volatile int* f = &g_flag[j];
                int v = *f;
                while (v == 0) { __nanosleep(40); v = *f; }
                __threadfence();                 // acquire
                const float2 val = (v == 2)
                    ? __ldcg(&g_incl[(size_t)j * DG_ + d])
                    : __ldcg(&g_agg [(size_t)j * DG_ + d]);
                cr = fmaf(mr, val.x, fmaf(-mi, val.y, cr));
                ci = fmaf(mi, val.x, fmaf( mr, val.y, ci));
                if (v == 2) break;               // prefix complete
                const float nmr = mr * p64r - mi * p64i;
                const float nmi = mr * p64i + mi * p64r;
                mr = nmr; mi = nmi;
                j -= NCHAIN;
            }
        }
        scarry[d] = make_float2(cr, ci);
    }

    __syncthreads();   // join: tile, E0, agg, carry all valid

    // ===== publish inclusive (h0, off the store path) ========================
    float hr, hi;
    if (h == 0) {
        const float2 cv = scarry[d];
        if (c > 0 && c < C_ - 1) {
            const float2 ag = sagg[d];
            const float inr = fmaf(p64r, cv.x, fmaf(-p64i, cv.y, ag.x));
            const float ini = fmaf(p64i, cv.x, fmaf( p64r, cv.y, ag.y));
            g_incl[(size_t)bid * DG_ + d] = make_float2(inr, ini);
            __threadfence();
            asm volatile("bar.sync 2, 128;" ::: "memory");
            if (d == 0) atomicExch(&g_flag[bid], 2);
        }
        hr = cv.x; hi = cv.y;                    // rescan half0 from carry
    } else {
        const float2 cv = scarry[d];
        const float2 e0 = se0[d];
        // carry into half1 = A^32 * carry + E0
        hr = fmaf(p32r, cv.x, fmaf(-p32i, cv.y, e0.x));
        hi = fmaf(p32i, cv.x, fmaf( p32r, cv.y, e0.y));
    }

    // ===== rescan my half from its true carry; stream outputs ================
    const float* sxh = sx + h * HALF_ * DG_ + d;
    float2* ob = out + ((size_t)b * T_ + (size_t)c * L_ + h * HALF_) * D_ + dglob;
    #pragma unroll
    for (int t = 0; t < HALF_; ++t) {
        const float xv = sxh[t * DG_];
        const float nr = fmaf(hr, ar, fmaf(-hi, ai, xv));
        const float ni = fmaf(hr, ai, hi * ar);
        hr = nr; hi = ni;
        __stcs(&ob[(size_t)t * D_], make_float2(nr, ni));
    }
}

// ---------------------------------------------------------------------------
// Inputs (metadata order): x [B*T*D] f32, A_real [D] f32, A_imag [D] f32.
// Output: [B, T, D, 2] f32.
// ---------------------------------------------------------------------------
extern "C" void kernel_launch(void* const* d_in, const int* in_sizes, int n_in,
                              void* d_out, int out_size)
{
    const float* x  = (const float*)d_in[0];
    const float* Ar = (const float*)d_in[1];
    const float* Ai = (const float*)d_in[2];
    float2* out = (float2*)d_out;

    init_flags_kernel<<<NBLK / THREADS, THREADS>>>();
    scan_kernel<<<NBLK, THREADS>>>(x, Ar, Ai, out);
}